// round 1
// baseline (speedup 1.0000x reference)
#include <cuda_runtime.h>
#include <math_constants.h>

#define BATCH 8
#define NTOK  1024
#define DIM   384
#define NH    12
#define HD    32

// ---------------- scratch (no allocs allowed) ----------------
__device__ float g_q [BATCH*NH*NTOK*HD];
__device__ float g_k [BATCH*NH*NTOK*HD];
__device__ float g_v [BATCH*NH*NTOK*HD];
__device__ float g_kc[BATCH*NH*NTOK*HD];
__device__ float g_vc[BATCH*NH*NTOK*HD];
__device__ float g_mid[BATCH*NTOK*DIM];

// ---------------- GEMM: C[M,N] = A[M,K] @ B[K,N] + bias ----------------
// MODE 0: scatter into g_q/g_k/g_v ([b,h,n,d] layout).  MODE 1: row-major Cout.
template<int KDIM, int NDIM, int MODE>
__global__ __launch_bounds__(256) void gemm_kernel(
    const float* __restrict__ A, const float* __restrict__ B,
    const float* __restrict__ bias, float* __restrict__ Cout)
{
    __shared__ float As[16][68];   // [k][m], padded, fp4-aligned pitch
    __shared__ float Bs[16][64];   // [k][n]

    const int m0  = blockIdx.y * 64;
    const int n0  = blockIdx.x * 64;
    const int tid = threadIdx.x;
    const int tx4 = (tid & 15) * 4;
    const int ty4 = (tid >> 4) * 4;

    const int am = tid >> 2;
    const int ak = (tid & 3) * 4;
    const int bk = tid >> 4;
    const int bn = (tid & 15) * 4;

    float acc[4][4];
#pragma unroll
    for (int i = 0; i < 4; i++)
#pragma unroll
        for (int j = 0; j < 4; j++) acc[i][j] = 0.f;

    for (int k0 = 0; k0 < KDIM; k0 += 16) {
        float4 av = *(const float4*)(A + (size_t)(m0 + am) * KDIM + k0 + ak);
        float4 bv = *(const float4*)(B + (size_t)(k0 + bk) * NDIM + n0 + bn);
        __syncthreads();
        As[ak + 0][am] = av.x; As[ak + 1][am] = av.y;
        As[ak + 2][am] = av.z; As[ak + 3][am] = av.w;
        *(float4*)&Bs[bk][bn] = bv;
        __syncthreads();
#pragma unroll
        for (int kk = 0; kk < 16; kk++) {
            float4 a4 = *(const float4*)&As[kk][ty4];
            float4 b4 = *(const float4*)&Bs[kk][tx4];
            float ar[4] = {a4.x, a4.y, a4.z, a4.w};
            float br[4] = {b4.x, b4.y, b4.z, b4.w};
#pragma unroll
            for (int i = 0; i < 4; i++)
#pragma unroll
                for (int j = 0; j < 4; j++) acc[i][j] += ar[i] * br[j];
        }
    }

#pragma unroll
    for (int i = 0; i < 4; i++) {
        const int row  = m0 + ty4 + i;
        const int bidx = row >> 10;          // batch
        const int n    = row & 1023;         // token
#pragma unroll
        for (int j = 0; j < 4; j++) {
            const int col = n0 + tx4 + j;
            float val = acc[i][j] + bias[col];
            if (MODE == 0) {
                const int s = col / DIM;
                const int r = col - s * DIM;
                const int h = r >> 5;
                const int d = r & 31;
                float* dst = (s == 0) ? g_q : ((s == 1) ? g_k : g_v);
                dst[(((bidx * NH + h) * NTOK + n) << 5) + d] = val;
            } else {
                Cout[(size_t)row * NDIM + col] = val;
            }
        }
    }
}

// ---------------- depthwise 3x3 SAME conv on K and V ----------------
__global__ __launch_bounds__(256) void dwconv_kernel(
    const float* __restrict__ w, const float* __restrict__ cb)
{
    const int idx = blockIdx.x * 256 + threadIdx.x;   // over B*NH*NTOK*HD
    const int d   = idx & 31;
    const int n   = (idx >> 5) & 1023;
    const int img = idx >> 15;                        // b*NH + h
    const int y = n >> 5, x = n & 31;
    const int base = img << 15;

    float accK = cb[d];
    float accV = accK;
#pragma unroll
    for (int ky = 0; ky < 3; ky++) {
        const int yy = y + ky - 1;
        if (yy < 0 || yy > 31) continue;
#pragma unroll
        for (int kx = 0; kx < 3; kx++) {
            const int xx = x + kx - 1;
            if (xx < 0 || xx > 31) continue;
            const float wv  = w[d * 9 + ky * 3 + kx];
            const int   off = base + (((yy << 5) | xx) << 5) + d;
            accK += g_k[off] * wv;
            accV += g_v[off] * wv;
        }
    }
    g_kc[idx] = accK;
    g_vc[idx] = accV;
}

// ---------------- fused biased softmax attention (flash style) ----------------
// grid: (96 = B*NH, 16 q-tiles of 64).  256 threads: thread = (row 0..63, c4 0..3),
// each thread owns 16 key columns of its row.
__global__ __launch_bounds__(256) void attn_kernel(const float* __restrict__ bias)
{
    __shared__ float Ks[64][33];
    __shared__ float Vs[64][33];

    const int bh  = blockIdx.x;
    const int qt  = blockIdx.y;
    const int b   = bh / NH;
    const int h   = bh - b * NH;
    const int tid = threadIdx.x;
    const int row = tid >> 2;
    const int c4  = tid & 3;
    const float scale = 0.17677669529663687f;   // 32^-0.5

    const float* qp = g_q + ((bh * NTOK + qt * 64 + row) << 5);
    float qreg[32];
#pragma unroll
    for (int d = 0; d < 32; d++) qreg[d] = qp[d] * scale;

    const float* brow = bias + (size_t)(h * NTOK + qt * 64 + row) * NTOK;

    float m = -CUDART_INF_F, l = 0.f;
    float oacc[32];
#pragma unroll
    for (int d = 0; d < 32; d++) oacc[d] = 0.f;

    for (int kt = 0; kt < 16; kt++) {
        __syncthreads();
#pragma unroll
        for (int i = 0; i < 8; i++) {
            const int e = tid + i * 256;
            const int r = e >> 5, c = e & 31;
            const int goff = ((bh * NTOK + kt * 64 + r) << 5) + c;
            Ks[r][c] = g_kc[goff];
            Vs[r][c] = g_vc[goff];
        }
        __syncthreads();

        float s[16];
        float mt = -CUDART_INF_F;
#pragma unroll
        for (int jj = 0; jj < 16; jj++) {
            const int j = c4 * 16 + jj;
            float acc = brow[kt * 64 + j];
#pragma unroll
            for (int d = 0; d < 32; d++) acc += qreg[d] * Ks[j][d];
            s[jj] = acc;
            mt = fmaxf(mt, acc);
        }
        mt = fmaxf(mt, __shfl_xor_sync(0xffffffffu, mt, 1));
        mt = fmaxf(mt, __shfl_xor_sync(0xffffffffu, mt, 2));
        const float mnew  = fmaxf(m, mt);
        const float alpha = __expf(m - mnew);

        float lsum = 0.f;
#pragma unroll
        for (int jj = 0; jj < 16; jj++) {
            const float p = __expf(s[jj] - mnew);
            s[jj] = p;
            lsum += p;
        }
        lsum += __shfl_xor_sync(0xffffffffu, lsum, 1);
        lsum += __shfl_xor_sync(0xffffffffu, lsum, 2);
        l = l * alpha + lsum;

#pragma unroll
        for (int d = 0; d < 32; d++) oacc[d] *= alpha;
#pragma unroll
        for (int jj = 0; jj < 16; jj++) {
            const int   j = c4 * 16 + jj;
            const float p = s[jj];
#pragma unroll
            for (int d = 0; d < 32; d++) oacc[d] += p * Vs[j][d];
        }
        m = mnew;
    }

#pragma unroll
    for (int d = 0; d < 32; d++) {
        oacc[d] += __shfl_xor_sync(0xffffffffu, oacc[d], 1);
        oacc[d] += __shfl_xor_sync(0xffffffffu, oacc[d], 2);
    }
    const float inv = 1.f / l;

    const int outb = ((b * NTOK + qt * 64 + row) * DIM) + h * HD + c4 * 8;
#pragma unroll
    for (int t = 0; t < 8; t++) g_mid[outb + t] = oacc[c4 * 8 + t] * inv;
}

// ---------------- launch ----------------
extern "C" void kernel_launch(void* const* d_in, const int* in_sizes, int n_in,
                              void* d_out, int out_size)
{
    const float* x          = (const float*)d_in[0];
    const float* w_qkv      = (const float*)d_in[1];
    const float* b_qkv      = (const float*)d_in[2];
    const float* conv_w     = (const float*)d_in[3];
    const float* conv_b     = (const float*)d_in[4];
    const float* w_proj     = (const float*)d_in[5];
    const float* b_proj     = (const float*)d_in[6];
    const float* bias_table = (const float*)d_in[7];
    float* out = (float*)d_out;

    void* pmid = nullptr;
    cudaGetSymbolAddress(&pmid, g_mid);

    // 1) fused QKV GEMM, scattered into [b,h,n,d] buffers
    gemm_kernel<DIM, 3 * DIM, 0><<<dim3(18, 128), 256>>>(x, w_qkv, b_qkv, nullptr);

    // 2) depthwise 3x3 conv on K and V
    dwconv_kernel<<<(BATCH * NH * NTOK * HD) / 256, 256>>>(conv_w, conv_b);

    // 3) fused biased-softmax attention -> g_mid [b,n,c]
    attn_kernel<<<dim3(BATCH * NH, 16), 256>>>(bias_table);

    // 4) output projection
    gemm_kernel<DIM, DIM, 1><<<dim3(6, 128), 256>>>(
        (const float*)pmid, w_proj, b_proj, out);
}

// round 2
// speedup vs baseline: 3.9548x; 3.9548x over previous
#include <cuda_runtime.h>
#include <math_constants.h>
#include <cstdint>

#define BATCH 8
#define NTOK  1024
#define DIM   384
#define NH    12
#define HD    32

// ---------------- scratch (no allocs allowed) ----------------
__device__ float g_q [BATCH*NH*NTOK*HD];
__device__ float g_k [BATCH*NH*NTOK*HD];
__device__ float g_v [BATCH*NH*NTOK*HD];
__device__ float g_kc[BATCH*NH*NTOK*HD];
__device__ float g_vc[BATCH*NH*NTOK*HD];
__device__ float g_mid[BATCH*NTOK*DIM];

// ---------------- GEMM: C[M,N] = A[M,K] @ B[K,N] + bias ----------------
template<int KDIM, int NDIM, int MODE>
__global__ __launch_bounds__(256) void gemm_kernel(
    const float* __restrict__ A, const float* __restrict__ B,
    const float* __restrict__ bias, float* __restrict__ Cout)
{
    __shared__ float As[16][68];
    __shared__ float Bs[16][64];

    const int m0  = blockIdx.y * 64;
    const int n0  = blockIdx.x * 64;
    const int tid = threadIdx.x;
    const int tx4 = (tid & 15) * 4;
    const int ty4 = (tid >> 4) * 4;

    const int am = tid >> 2;
    const int ak = (tid & 3) * 4;
    const int bk = tid >> 4;
    const int bn = (tid & 15) * 4;

    float acc[4][4];
#pragma unroll
    for (int i = 0; i < 4; i++)
#pragma unroll
        for (int j = 0; j < 4; j++) acc[i][j] = 0.f;

    for (int k0 = 0; k0 < KDIM; k0 += 16) {
        float4 av = *(const float4*)(A + (size_t)(m0 + am) * KDIM + k0 + ak);
        float4 bv = *(const float4*)(B + (size_t)(k0 + bk) * NDIM + n0 + bn);
        __syncthreads();
        As[ak + 0][am] = av.x; As[ak + 1][am] = av.y;
        As[ak + 2][am] = av.z; As[ak + 3][am] = av.w;
        *(float4*)&Bs[bk][bn] = bv;
        __syncthreads();
#pragma unroll
        for (int kk = 0; kk < 16; kk++) {
            float4 a4 = *(const float4*)&As[kk][ty4];
            float4 b4 = *(const float4*)&Bs[kk][tx4];
            float ar[4] = {a4.x, a4.y, a4.z, a4.w};
            float br[4] = {b4.x, b4.y, b4.z, b4.w};
#pragma unroll
            for (int i = 0; i < 4; i++)
#pragma unroll
                for (int j = 0; j < 4; j++) acc[i][j] += ar[i] * br[j];
        }
    }

#pragma unroll
    for (int i = 0; i < 4; i++) {
        const int row  = m0 + ty4 + i;
        const int bidx = row >> 10;
        const int n    = row & 1023;
#pragma unroll
        for (int j = 0; j < 4; j++) {
            const int col = n0 + tx4 + j;
            float val = acc[i][j] + bias[col];
            if (MODE == 0) {
                const int s = col / DIM;
                const int r = col - s * DIM;
                const int h = r >> 5;
                const int d = r & 31;
                float* dst = (s == 0) ? g_q : ((s == 1) ? g_k : g_v);
                dst[(((bidx * NH + h) * NTOK + n) << 5) + d] = val;
            } else {
                Cout[(size_t)row * NDIM + col] = val;
            }
        }
    }
}

// ---------------- depthwise 3x3 SAME conv on K and V ----------------
__global__ __launch_bounds__(256) void dwconv_kernel(
    const float* __restrict__ w, const float* __restrict__ cb)
{
    const int idx = blockIdx.x * 256 + threadIdx.x;
    const int d   = idx & 31;
    const int n   = (idx >> 5) & 1023;
    const int img = idx >> 15;
    const int y = n >> 5, x = n & 31;
    const int base = img << 15;

    float accK = cb[d];
    float accV = accK;
#pragma unroll
    for (int ky = 0; ky < 3; ky++) {
        const int yy = y + ky - 1;
        if (yy < 0 || yy > 31) continue;
#pragma unroll
        for (int kx = 0; kx < 3; kx++) {
            const int xx = x + kx - 1;
            if (xx < 0 || xx > 31) continue;
            const float wv  = w[d * 9 + ky * 3 + kx];
            const int   off = base + (((yy << 5) | xx) << 5) + d;
            accK += g_k[off] * wv;
            accV += g_v[off] * wv;
        }
    }
    g_kc[idx] = accK;
    g_vc[idx] = accV;
}

// ---------------- tf32 mma helpers ----------------
__device__ __forceinline__ uint32_t f2tf(float f) {
    uint32_t r;
    asm("cvt.rna.tf32.f32 %0, %1;" : "=r"(r) : "f"(f));
    return r;
}

__device__ __forceinline__ void mma_tf32(float c[4], const uint32_t a[4], const uint32_t b[2]) {
    asm volatile(
        "mma.sync.aligned.m16n8k8.row.col.f32.tf32.tf32.f32 "
        "{%0,%1,%2,%3},{%4,%5,%6,%7},{%8,%9},{%0,%1,%2,%3};"
        : "+f"(c[0]), "+f"(c[1]), "+f"(c[2]), "+f"(c[3])
        : "r"(a[0]), "r"(a[1]), "r"(a[2]), "r"(a[3]), "r"(b[0]), "r"(b[1]));
}

// ---------------- flash attention on tensor cores (tf32) ----------------
// grid (96, 16): (b*NH, q-tile of 64). 128 threads = 4 warps, each warp owns
// 16 query rows. m16n8k8 tf32 MMAs for S = bias + scale*Q*K^T and O += P*V.
__global__ __launch_bounds__(128) void attn_mma_kernel(const float* __restrict__ bias)
{
    __shared__ uint32_t Ksm[64][36];        // pitch 36: conflict-free B-frag loads
    __shared__ uint32_t Vsm[64][36];
    __shared__ uint32_t Psm[4][16][68];     // warp-private P staging

    const int bh  = blockIdx.x;
    const int qt  = blockIdx.y;
    const int b   = bh / NH;
    const int h   = bh - b * NH;
    const int tid  = threadIdx.x;
    const int warp = tid >> 5;
    const int lane = tid & 31;
    const int g = lane >> 2;      // group (row within octet)
    const int q = lane & 3;       // quad lane
    const float scale = 0.17677669529663687f;  // 32^-0.5

    const int r0 = qt * 64 + warp * 16 + g;   // query rows this thread owns
    const int r1 = r0 + 8;

    // Q fragments: 4 k-steps of 8, scale folded in, tf32
    uint32_t qa[4][4];
    {
        const float* q0 = g_q + ((bh * NTOK + r0) << 5);
        const float* q1 = g_q + ((bh * NTOK + r1) << 5);
#pragma unroll
        for (int kk = 0; kk < 4; kk++) {
            qa[kk][0] = f2tf(q0[kk * 8 + q]     * scale);
            qa[kk][1] = f2tf(q1[kk * 8 + q]     * scale);
            qa[kk][2] = f2tf(q0[kk * 8 + q + 4] * scale);
            qa[kk][3] = f2tf(q1[kk * 8 + q + 4] * scale);
        }
    }

    const float* br0 = bias + ((size_t)h * NTOK + r0) * NTOK;
    const float* br1 = bias + ((size_t)h * NTOK + r1) * NTOK;

    float m0 = -CUDART_INF_F, m1 = -CUDART_INF_F, l0 = 0.f, l1 = 0.f;
    float o[4][4];
#pragma unroll
    for (int nn = 0; nn < 4; nn++)
#pragma unroll
        for (int i = 0; i < 4; i++) o[nn][i] = 0.f;

    for (int kt = 0; kt < 16; kt++) {
        __syncthreads();
        // stage K/V tile (64 keys x 32 dims) as tf32 bits
#pragma unroll
        for (int i = 0; i < 16; i++) {
            const int e = tid + i * 128;
            const int r = e >> 5, c = e & 31;
            const int goff = ((bh * NTOK + kt * 64 + r) << 5) + c;
            Ksm[r][c] = f2tf(g_kc[goff]);
            Vsm[r][c] = f2tf(g_vc[goff]);
        }
        __syncthreads();

        // S = bias  (accumulator-layout loads: rows r0/r1, cols 2q,2q+1)
        float s[8][4];
#pragma unroll
        for (int nn = 0; nn < 8; nn++) {
            const int col = kt * 64 + nn * 8 + 2 * q;
            float2 bb0 = *(const float2*)(br0 + col);
            float2 bb1 = *(const float2*)(br1 + col);
            s[nn][0] = bb0.x; s[nn][1] = bb0.y;
            s[nn][2] = bb1.x; s[nn][3] = bb1.y;
        }
        // S += scale * Q K^T
#pragma unroll
        for (int kk = 0; kk < 4; kk++) {
#pragma unroll
            for (int nn = 0; nn < 8; nn++) {
                uint32_t bf[2];
                bf[0] = Ksm[nn * 8 + g][kk * 8 + q];
                bf[1] = Ksm[nn * 8 + g][kk * 8 + q + 4];
                mma_tf32(s[nn], qa[kk], bf);
            }
        }

        // fragment-level online softmax (rows r0 -> c0,c1 ; r1 -> c2,c3)
        float mt0 = -CUDART_INF_F, mt1 = -CUDART_INF_F;
#pragma unroll
        for (int nn = 0; nn < 8; nn++) {
            mt0 = fmaxf(mt0, fmaxf(s[nn][0], s[nn][1]));
            mt1 = fmaxf(mt1, fmaxf(s[nn][2], s[nn][3]));
        }
        mt0 = fmaxf(mt0, __shfl_xor_sync(0xffffffffu, mt0, 1));
        mt0 = fmaxf(mt0, __shfl_xor_sync(0xffffffffu, mt0, 2));
        mt1 = fmaxf(mt1, __shfl_xor_sync(0xffffffffu, mt1, 1));
        mt1 = fmaxf(mt1, __shfl_xor_sync(0xffffffffu, mt1, 2));

        const float mn0 = fmaxf(m0, mt0);
        const float mn1 = fmaxf(m1, mt1);
        const float a0  = __expf(m0 - mn0);
        const float a1  = __expf(m1 - mn1);

        float ls0 = 0.f, ls1 = 0.f;
#pragma unroll
        for (int nn = 0; nn < 8; nn++) {
            const float p00 = __expf(s[nn][0] - mn0);
            const float p01 = __expf(s[nn][1] - mn0);
            const float p10 = __expf(s[nn][2] - mn1);
            const float p11 = __expf(s[nn][3] - mn1);
            ls0 += p00 + p01;
            ls1 += p10 + p11;
            *(uint2*)&Psm[warp][g    ][nn * 8 + 2 * q] = make_uint2(f2tf(p00), f2tf(p01));
            *(uint2*)&Psm[warp][g + 8][nn * 8 + 2 * q] = make_uint2(f2tf(p10), f2tf(p11));
        }
        ls0 += __shfl_xor_sync(0xffffffffu, ls0, 1);
        ls0 += __shfl_xor_sync(0xffffffffu, ls0, 2);
        ls1 += __shfl_xor_sync(0xffffffffu, ls1, 1);
        ls1 += __shfl_xor_sync(0xffffffffu, ls1, 2);

        l0 = l0 * a0 + ls0;
        l1 = l1 * a1 + ls1;
        m0 = mn0;
        m1 = mn1;

        // rescale O
#pragma unroll
        for (int nn = 0; nn < 4; nn++) {
            o[nn][0] *= a0; o[nn][1] *= a0;
            o[nn][2] *= a1; o[nn][3] *= a1;
        }

        __syncwarp();
        // O += P V
#pragma unroll
        for (int kk = 0; kk < 8; kk++) {
            uint32_t pa[4];
            pa[0] = Psm[warp][g    ][kk * 8 + q];
            pa[1] = Psm[warp][g + 8][kk * 8 + q];
            pa[2] = Psm[warp][g    ][kk * 8 + q + 4];
            pa[3] = Psm[warp][g + 8][kk * 8 + q + 4];
#pragma unroll
            for (int nn = 0; nn < 4; nn++) {
                uint32_t bf[2];
                bf[0] = Vsm[kk * 8 + q    ][nn * 8 + g];
                bf[1] = Vsm[kk * 8 + q + 4][nn * 8 + g];
                mma_tf32(o[nn], pa, bf);
            }
        }
        __syncwarp();
    }

    // epilogue: normalize and write g_mid [b, n, c]
    const float inv0 = 1.f / l0;
    const float inv1 = 1.f / l1;
    const int base0 = (b * NTOK + r0) * DIM + h * HD;
    const int base1 = (b * NTOK + r1) * DIM + h * HD;
#pragma unroll
    for (int nn = 0; nn < 4; nn++) {
        float2 w0 = make_float2(o[nn][0] * inv0, o[nn][1] * inv0);
        float2 w1 = make_float2(o[nn][2] * inv1, o[nn][3] * inv1);
        *(float2*)&g_mid[base0 + nn * 8 + 2 * q] = w0;
        *(float2*)&g_mid[base1 + nn * 8 + 2 * q] = w1;
    }
}

// ---------------- launch ----------------
extern "C" void kernel_launch(void* const* d_in, const int* in_sizes, int n_in,
                              void* d_out, int out_size)
{
    const float* x          = (const float*)d_in[0];
    const float* w_qkv      = (const float*)d_in[1];
    const float* b_qkv      = (const float*)d_in[2];
    const float* conv_w     = (const float*)d_in[3];
    const float* conv_b     = (const float*)d_in[4];
    const float* w_proj     = (const float*)d_in[5];
    const float* b_proj     = (const float*)d_in[6];
    const float* bias_table = (const float*)d_in[7];
    float* out = (float*)d_out;

    void* pmid = nullptr;
    cudaGetSymbolAddress(&pmid, g_mid);

    // 1) fused QKV GEMM, scattered into [b,h,n,d] buffers
    gemm_kernel<DIM, 3 * DIM, 0><<<dim3(18, 128), 256>>>(x, w_qkv, b_qkv, nullptr);

    // 2) depthwise 3x3 conv on K and V
    dwconv_kernel<<<(BATCH * NH * NTOK * HD) / 256, 256>>>(conv_w, conv_b);

    // 3) tensor-core flash attention -> g_mid [b,n,c]
    attn_mma_kernel<<<dim3(BATCH * NH, 16), 128>>>(bias_table);

    // 4) output projection
    gemm_kernel<DIM, DIM, 1><<<dim3(6, 128), 256>>>(
        (const float*)pmid, w_proj, b_proj, out);
}

// round 3
// speedup vs baseline: 5.6429x; 1.4269x over previous
#include <cuda_runtime.h>
#include <math_constants.h>
#include <cstdint>

#define BATCH 8
#define NTOK  1024
#define DIM   384
#define NH    12
#define HD    32

// ---------------- scratch (no allocs allowed) ----------------
__device__ float g_q [BATCH*NH*NTOK*HD];
__device__ float g_k [BATCH*NH*NTOK*HD];
__device__ float g_v [BATCH*NH*NTOK*HD];
__device__ float g_kc[BATCH*NH*NTOK*HD];
__device__ float g_vc[BATCH*NH*NTOK*HD];
__device__ float g_mid[BATCH*NTOK*DIM];

// ---------------- tf32 mma helpers ----------------
__device__ __forceinline__ uint32_t f2tf(float f) {
    uint32_t r;
    asm("cvt.rna.tf32.f32 %0, %1;" : "=r"(r) : "f"(f));
    return r;
}

__device__ __forceinline__ void mma_tf32(float c[4], const uint32_t a[4], const uint32_t b[2]) {
    asm volatile(
        "mma.sync.aligned.m16n8k8.row.col.f32.tf32.tf32.f32 "
        "{%0,%1,%2,%3},{%4,%5,%6,%7},{%8,%9},{%0,%1,%2,%3};"
        : "+f"(c[0]), "+f"(c[1]), "+f"(c[2]), "+f"(c[3])
        : "r"(a[0]), "r"(a[1]), "r"(a[2]), "r"(a[3]), "r"(b[0]), "r"(b[1]));
}

// ---------------- tensor-core GEMM: C[M,N] = A[M,384] @ B[384,N] + bias ----
// Block tile 128(M) x 64(N), 8 warps of 32x32, tf32 mma, double-buffered.
// MODE 0: scatter into g_q/g_k/g_v ([b,h,n,d]).  MODE 1: row-major Cout.
template<int NDIM, int MODE>
__global__ __launch_bounds__(256) void gemm_mma(
    const float* __restrict__ A, const float* __restrict__ B,
    const float* __restrict__ bias, float* __restrict__ Cout)
{
    constexpr int KDIM = 384;
    constexpr int NK   = KDIM / 16;   // 24 k-panels of 16

    __shared__ uint32_t As[2][128][20];   // [m][k] pitch 20: frag loads conflict-free
    __shared__ uint32_t Bs[2][16][72];    // [k][n] pitch 72: frag loads + STS.128 conflict-free

    const int m0  = blockIdx.y * 128;
    const int n0  = blockIdx.x * 64;
    const int tid  = threadIdx.x;
    const int warp = tid >> 5;
    const int lane = tid & 31;
    const int g = lane >> 2;
    const int q = lane & 3;
    const int wm = (warp & 3) * 32;
    const int wn = (warp >> 2) * 32;

    // A staging: 2 float4 per thread. f = tid*2+j: row = f>>2, kc = (f&3)*4
    const int ar0 = (tid * 2)     >> 2, akc0 = ((tid * 2)     & 3) * 4;
    const int ar1 = (tid * 2 + 1) >> 2, akc1 = ((tid * 2 + 1) & 3) * 4;
    // B staging: 1 float4 per thread: kk = tid>>4, nc = (tid&15)*4
    const int bkk = tid >> 4;
    const int bnc = (tid & 15) * 4;

    float acc[2][4][4];
#pragma unroll
    for (int mi = 0; mi < 2; mi++)
#pragma unroll
        for (int ni = 0; ni < 4; ni++)
#pragma unroll
            for (int i = 0; i < 4; i++) acc[mi][ni][i] = 0.f;

    float4 pa0, pa1, pb;

    // prologue: load panel 0
    pa0 = *(const float4*)(A + (size_t)(m0 + ar0) * KDIM + akc0);
    pa1 = *(const float4*)(A + (size_t)(m0 + ar1) * KDIM + akc1);
    pb  = *(const float4*)(B + (size_t)bkk * NDIM + n0 + bnc);

    {
        As[0][ar0][akc0 + 0] = f2tf(pa0.x); As[0][ar0][akc0 + 1] = f2tf(pa0.y);
        As[0][ar0][akc0 + 2] = f2tf(pa0.z); As[0][ar0][akc0 + 3] = f2tf(pa0.w);
        As[0][ar1][akc1 + 0] = f2tf(pa1.x); As[0][ar1][akc1 + 1] = f2tf(pa1.y);
        As[0][ar1][akc1 + 2] = f2tf(pa1.z); As[0][ar1][akc1 + 3] = f2tf(pa1.w);
        uint4 bt = make_uint4(f2tf(pb.x), f2tf(pb.y), f2tf(pb.z), f2tf(pb.w));
        *(uint4*)&Bs[0][bkk][bnc] = bt;
    }
    __syncthreads();

    for (int kb = 0; kb < NK; kb++) {
        const int cur = kb & 1;
        const bool has_next = (kb + 1) < NK;

        if (has_next) {
            const int k0 = (kb + 1) * 16;
            pa0 = *(const float4*)(A + (size_t)(m0 + ar0) * KDIM + k0 + akc0);
            pa1 = *(const float4*)(A + (size_t)(m0 + ar1) * KDIM + k0 + akc1);
            pb  = *(const float4*)(B + (size_t)(k0 + bkk) * NDIM + n0 + bnc);
        }

#pragma unroll
        for (int s = 0; s < 2; s++) {
            const int koff = s * 8;
            uint32_t af[2][4];
#pragma unroll
            for (int mi = 0; mi < 2; mi++) {
                const int r = wm + mi * 16 + g;
                af[mi][0] = As[cur][r    ][koff + q];
                af[mi][1] = As[cur][r + 8][koff + q];
                af[mi][2] = As[cur][r    ][koff + q + 4];
                af[mi][3] = As[cur][r + 8][koff + q + 4];
            }
            uint32_t bf[4][2];
#pragma unroll
            for (int ni = 0; ni < 4; ni++) {
                const int n = wn + ni * 8 + g;
                bf[ni][0] = Bs[cur][koff + q    ][n];
                bf[ni][1] = Bs[cur][koff + q + 4][n];
            }
#pragma unroll
            for (int mi = 0; mi < 2; mi++)
#pragma unroll
                for (int ni = 0; ni < 4; ni++)
                    mma_tf32(acc[mi][ni], af[mi], bf[ni]);
        }

        if (has_next) {
            const int nxt = cur ^ 1;
            As[nxt][ar0][akc0 + 0] = f2tf(pa0.x); As[nxt][ar0][akc0 + 1] = f2tf(pa0.y);
            As[nxt][ar0][akc0 + 2] = f2tf(pa0.z); As[nxt][ar0][akc0 + 3] = f2tf(pa0.w);
            As[nxt][ar1][akc1 + 0] = f2tf(pa1.x); As[nxt][ar1][akc1 + 1] = f2tf(pa1.y);
            As[nxt][ar1][akc1 + 2] = f2tf(pa1.z); As[nxt][ar1][akc1 + 3] = f2tf(pa1.w);
            uint4 bt = make_uint4(f2tf(pb.x), f2tf(pb.y), f2tf(pb.z), f2tf(pb.w));
            *(uint4*)&Bs[nxt][bkk][bnc] = bt;
        }
        __syncthreads();
    }

    // epilogue: bias add + store
#pragma unroll
    for (int mi = 0; mi < 2; mi++) {
#pragma unroll
        for (int rr = 0; rr < 2; rr++) {
            const int row  = m0 + wm + mi * 16 + g + rr * 8;
            const int bidx = row >> 10;
            const int n    = row & 1023;
#pragma unroll
            for (int ni = 0; ni < 4; ni++) {
                const int col = n0 + wn + ni * 8 + 2 * q;
                const float v0 = acc[mi][ni][rr * 2]     + bias[col];
                const float v1 = acc[mi][ni][rr * 2 + 1] + bias[col + 1];
                if (MODE == 0) {
                    const int s = col / DIM;
                    const int r = col - s * DIM;
                    const int h = r >> 5;
                    const int d = r & 31;
                    float* dst = (s == 0) ? g_q : ((s == 1) ? g_k : g_v);
                    *(float2*)&dst[(((bidx * NH + h) * NTOK + n) << 5) + d] =
                        make_float2(v0, v1);
                } else {
                    *(float2*)&Cout[(size_t)row * NDIM + col] = make_float2(v0, v1);
                }
            }
        }
    }
}

// ---------------- depthwise 3x3 SAME conv on K and V ----------------
__global__ __launch_bounds__(256) void dwconv_kernel(
    const float* __restrict__ w, const float* __restrict__ cb)
{
    const int idx = blockIdx.x * 256 + threadIdx.x;
    const int d   = idx & 31;
    const int n   = (idx >> 5) & 1023;
    const int img = idx >> 15;
    const int y = n >> 5, x = n & 31;
    const int base = img << 15;

    float accK = cb[d];
    float accV = accK;
#pragma unroll
    for (int ky = 0; ky < 3; ky++) {
        const int yy = y + ky - 1;
        if (yy < 0 || yy > 31) continue;
#pragma unroll
        for (int kx = 0; kx < 3; kx++) {
            const int xx = x + kx - 1;
            if (xx < 0 || xx > 31) continue;
            const float wv  = w[d * 9 + ky * 3 + kx];
            const int   off = base + (((yy << 5) | xx) << 5) + d;
            accK += g_k[off] * wv;
            accV += g_v[off] * wv;
        }
    }
    g_kc[idx] = accK;
    g_vc[idx] = accV;
}

// ---------------- flash attention on tensor cores (tf32) ----------------
__global__ __launch_bounds__(128) void attn_mma_kernel(const float* __restrict__ bias)
{
    __shared__ uint32_t Ksm[64][36];
    __shared__ uint32_t Vsm[64][36];
    __shared__ uint32_t Psm[4][16][68];

    const int bh  = blockIdx.x;
    const int qt  = blockIdx.y;
    const int b   = bh / NH;
    const int h   = bh - b * NH;
    const int tid  = threadIdx.x;
    const int warp = tid >> 5;
    const int lane = tid & 31;
    const int g = lane >> 2;
    const int q = lane & 3;
    const float scale = 0.17677669529663687f;

    const int r0 = qt * 64 + warp * 16 + g;
    const int r1 = r0 + 8;

    uint32_t qa[4][4];
    {
        const float* q0 = g_q + ((bh * NTOK + r0) << 5);
        const float* q1 = g_q + ((bh * NTOK + r1) << 5);
#pragma unroll
        for (int kk = 0; kk < 4; kk++) {
            qa[kk][0] = f2tf(q0[kk * 8 + q]     * scale);
            qa[kk][1] = f2tf(q1[kk * 8 + q]     * scale);
            qa[kk][2] = f2tf(q0[kk * 8 + q + 4] * scale);
            qa[kk][3] = f2tf(q1[kk * 8 + q + 4] * scale);
        }
    }

    const float* br0 = bias + ((size_t)h * NTOK + r0) * NTOK;
    const float* br1 = bias + ((size_t)h * NTOK + r1) * NTOK;

    float m0 = -CUDART_INF_F, m1 = -CUDART_INF_F, l0 = 0.f, l1 = 0.f;
    float o[4][4];
#pragma unroll
    for (int nn = 0; nn < 4; nn++)
#pragma unroll
        for (int i = 0; i < 4; i++) o[nn][i] = 0.f;

    for (int kt = 0; kt < 16; kt++) {
        __syncthreads();
#pragma unroll
        for (int i = 0; i < 16; i++) {
            const int e = tid + i * 128;
            const int r = e >> 5, c = e & 31;
            const int goff = ((bh * NTOK + kt * 64 + r) << 5) + c;
            Ksm[r][c] = f2tf(g_kc[goff]);
            Vsm[r][c] = f2tf(g_vc[goff]);
        }
        __syncthreads();

        float s[8][4];
#pragma unroll
        for (int nn = 0; nn < 8; nn++) {
            const int col = kt * 64 + nn * 8 + 2 * q;
            float2 bb0 = *(const float2*)(br0 + col);
            float2 bb1 = *(const float2*)(br1 + col);
            s[nn][0] = bb0.x; s[nn][1] = bb0.y;
            s[nn][2] = bb1.x; s[nn][3] = bb1.y;
        }
#pragma unroll
        for (int kk = 0; kk < 4; kk++) {
#pragma unroll
            for (int nn = 0; nn < 8; nn++) {
                uint32_t bf[2];
                bf[0] = Ksm[nn * 8 + g][kk * 8 + q];
                bf[1] = Ksm[nn * 8 + g][kk * 8 + q + 4];
                mma_tf32(s[nn], qa[kk], bf);
            }
        }

        float mt0 = -CUDART_INF_F, mt1 = -CUDART_INF_F;
#pragma unroll
        for (int nn = 0; nn < 8; nn++) {
            mt0 = fmaxf(mt0, fmaxf(s[nn][0], s[nn][1]));
            mt1 = fmaxf(mt1, fmaxf(s[nn][2], s[nn][3]));
        }
        mt0 = fmaxf(mt0, __shfl_xor_sync(0xffffffffu, mt0, 1));
        mt0 = fmaxf(mt0, __shfl_xor_sync(0xffffffffu, mt0, 2));
        mt1 = fmaxf(mt1, __shfl_xor_sync(0xffffffffu, mt1, 1));
        mt1 = fmaxf(mt1, __shfl_xor_sync(0xffffffffu, mt1, 2));

        const float mn0 = fmaxf(m0, mt0);
        const float mn1 = fmaxf(m1, mt1);
        const float a0  = __expf(m0 - mn0);
        const float a1  = __expf(m1 - mn1);

        float ls0 = 0.f, ls1 = 0.f;
#pragma unroll
        for (int nn = 0; nn < 8; nn++) {
            const float p00 = __expf(s[nn][0] - mn0);
            const float p01 = __expf(s[nn][1] - mn0);
            const float p10 = __expf(s[nn][2] - mn1);
            const float p11 = __expf(s[nn][3] - mn1);
            ls0 += p00 + p01;
            ls1 += p10 + p11;
            *(uint2*)&Psm[warp][g    ][nn * 8 + 2 * q] = make_uint2(f2tf(p00), f2tf(p01));
            *(uint2*)&Psm[warp][g + 8][nn * 8 + 2 * q] = make_uint2(f2tf(p10), f2tf(p11));
        }
        ls0 += __shfl_xor_sync(0xffffffffu, ls0, 1);
        ls0 += __shfl_xor_sync(0xffffffffu, ls0, 2);
        ls1 += __shfl_xor_sync(0xffffffffu, ls1, 1);
        ls1 += __shfl_xor_sync(0xffffffffu, ls1, 2);

        l0 = l0 * a0 + ls0;
        l1 = l1 * a1 + ls1;
        m0 = mn0;
        m1 = mn1;

#pragma unroll
        for (int nn = 0; nn < 4; nn++) {
            o[nn][0] *= a0; o[nn][1] *= a0;
            o[nn][2] *= a1; o[nn][3] *= a1;
        }

        __syncwarp();
#pragma unroll
        for (int kk = 0; kk < 8; kk++) {
            uint32_t pa[4];
            pa[0] = Psm[warp][g    ][kk * 8 + q];
            pa[1] = Psm[warp][g + 8][kk * 8 + q];
            pa[2] = Psm[warp][g    ][kk * 8 + q + 4];
            pa[3] = Psm[warp][g + 8][kk * 8 + q + 4];
#pragma unroll
            for (int nn = 0; nn < 4; nn++) {
                uint32_t bf[2];
                bf[0] = Vsm[kk * 8 + q    ][nn * 8 + g];
                bf[1] = Vsm[kk * 8 + q + 4][nn * 8 + g];
                mma_tf32(o[nn], pa, bf);
            }
        }
        __syncwarp();
    }

    const float inv0 = 1.f / l0;
    const float inv1 = 1.f / l1;
    const int base0 = (b * NTOK + r0) * DIM + h * HD;
    const int base1 = (b * NTOK + r1) * DIM + h * HD;
#pragma unroll
    for (int nn = 0; nn < 4; nn++) {
        *(float2*)&g_mid[base0 + nn * 8 + 2 * q] =
            make_float2(o[nn][0] * inv0, o[nn][1] * inv0);
        *(float2*)&g_mid[base1 + nn * 8 + 2 * q] =
            make_float2(o[nn][2] * inv1, o[nn][3] * inv1);
    }
}

// ---------------- launch ----------------
extern "C" void kernel_launch(void* const* d_in, const int* in_sizes, int n_in,
                              void* d_out, int out_size)
{
    const float* x          = (const float*)d_in[0];
    const float* w_qkv      = (const float*)d_in[1];
    const float* b_qkv      = (const float*)d_in[2];
    const float* conv_w     = (const float*)d_in[3];
    const float* conv_b     = (const float*)d_in[4];
    const float* w_proj     = (const float*)d_in[5];
    const float* b_proj     = (const float*)d_in[6];
    const float* bias_table = (const float*)d_in[7];
    float* out = (float*)d_out;

    void* pmid = nullptr;
    cudaGetSymbolAddress(&pmid, g_mid);

    // 1) fused QKV GEMM (tensor cores), scattered into [b,h,n,d] buffers
    gemm_mma<3 * DIM, 0><<<dim3(18, 64), 256>>>(x, w_qkv, b_qkv, nullptr);

    // 2) depthwise 3x3 conv on K and V
    dwconv_kernel<<<(BATCH * NH * NTOK * HD) / 256, 256>>>(conv_w, conv_b);

    // 3) tensor-core flash attention -> g_mid [b,n,c]
    attn_mma_kernel<<<dim3(BATCH * NH, 16), 128>>>(bias_table);

    // 4) output projection (tensor cores)
    gemm_mma<DIM, 1><<<dim3(6, 64), 256>>>(
        (const float*)pmid, w_proj, b_proj, out);
}